// round 12
// baseline (speedup 1.0000x reference)
#include <cuda_runtime.h>
#include <cuda_bf16.h>

#define REC      2048
#define BATCH    64
#define RSTEPS   512
#define EDIM     512
#define KTOP     819
#define GRID     128
#define PTHREADS 512
#define NBAR     (1 + 2*RSTEPS)

// ---- static device scratch ----
__device__ __nv_bfloat16 g_Rh[BATCH * REC];
__device__ __nv_bfloat16 g_Rl[BATCH * REC];
__device__ __nv_bfloat16 g_WhT[(size_t)REC * REC];        // Wr hi, [n][k]
__device__ __nv_bfloat16 g_WlT[(size_t)REC * REC];        // Wr lo, [n][k]
__device__ __nv_bfloat16 g_WiTh[(size_t)REC * EDIM];      // Wi hi, [n][k]
__device__ __nv_bfloat16 g_WiTl[(size_t)REC * EDIM];      // Wi lo, [n][k]
__device__ __nv_bfloat16 g_Xh[(size_t)BATCH * RSTEPS * EDIM];
__device__ __nv_bfloat16 g_Xl[(size_t)BATCH * RSTEPS * EDIM];
__device__ float g_part[8 * BATCH * REC];
__device__ float g_U[(size_t)RSTEPS * BATCH * REC];
__device__ unsigned g_bar;

__device__ __forceinline__ unsigned keyOf(float f) {
    unsigned b = __float_as_uint(f);
    return (b & 0x80000000u) ? ~b : (b | 0x80000000u);
}
__device__ __forceinline__ float ftanh(float x) {
    float t = __expf(2.0f * x);
    return 1.0f - __fdividef(2.0f, t + 1.0f);
}

// ---- tensor-core primitives (proven) ----
__device__ __forceinline__ void ldsm4v(unsigned* r, unsigned addr) {
    asm volatile("ldmatrix.sync.aligned.m8n8.x4.shared.b16 {%0,%1,%2,%3}, [%4];"
                 : "=r"(r[0]), "=r"(r[1]), "=r"(r[2]), "=r"(r[3]) : "r"(addr));
}
__device__ __forceinline__ void mma16816(float* d, const unsigned* a,
                                         unsigned b0, unsigned b1) {
    asm volatile("mma.sync.aligned.m16n8k16.row.col.f32.bf16.bf16.f32 "
                 "{%0,%1,%2,%3}, {%4,%5,%6,%7}, {%8,%9}, {%0,%1,%2,%3};"
                 : "+f"(d[0]), "+f"(d[1]), "+f"(d[2]), "+f"(d[3])
                 : "r"(a[0]), "r"(a[1]), "r"(a[2]), "r"(a[3]), "r"(b0), "r"(b1));
}

// ---------------------------------------------------------------------------
// 64(M) x 128(N) x (nsub*64)(K) tile, 512 threads (16 warps: 4M x 4N, 32
// cols/warp). Register prefetch of ksub+1. Fragment addressing identical to
// the proven 8-warp tile; only the warp->(m,n) map and loader split changed.
// THREE=true : out = Ah@Bh + Al@Bh + Ah@Bl ; THREE=false: out = Ah@Bh + Al@Bh
// ---------------------------------------------------------------------------
template <bool THREE>
__device__ __forceinline__ void mma_tile_64x128_w16(
    const __nv_bfloat16* __restrict__ Ah, const __nv_bfloat16* __restrict__ Al,
    size_t strideA,
    const __nv_bfloat16* __restrict__ Bh, const __nv_bfloat16* __restrict__ Bl,
    size_t strideB,
    int nsub,
    float* __restrict__ outBase, size_t strideO,
    __nv_bfloat16 (*As_h)[72], __nv_bfloat16 (*As_l)[72], __nv_bfloat16 (*Bs)[72],
    int tid)
{
    const int lane = tid & 31, wid = tid >> 5;
    const int m0w = (wid & 3) << 4;          // 4 warps along M, 16 rows each
    const int n0w = (wid >> 2) << 5;         // 4 warps along N, 32 cols each
    const unsigned sAh = (unsigned)__cvta_generic_to_shared(&As_h[0][0]);
    const unsigned sAl = (unsigned)__cvta_generic_to_shared(&As_l[0][0]);
    const unsigned sB  = (unsigned)__cvta_generic_to_shared(&Bs[0][0]);
    const unsigned lrow = (lane & 15);
    const unsigned lcol = (lane >> 4) << 3;

    // loaders: A 64x64 = 512 uint4 (1/thread); B 128x64 = 1024 uint4 (2/thread)
    const int ar = tid >> 3, ac = (tid & 7) << 3;
    const int br = tid >> 3;

    float acc[4][4];
    #pragma unroll
    for (int f = 0; f < 4; f++)
        #pragma unroll
        for (int q = 0; q < 4; q++) acc[f][q] = 0.0f;

    uint4 pAh, pAl, pBh[2], pBl[2];
    pAh = *(const uint4*)&Ah[(size_t)ar * strideA + ac];
    pAl = *(const uint4*)&Al[(size_t)ar * strideA + ac];
    pBh[0] = *(const uint4*)&Bh[(size_t)br * strideB + ac];
    pBh[1] = *(const uint4*)&Bh[(size_t)(br + 64) * strideB + ac];
    if (THREE) {
        pBl[0] = *(const uint4*)&Bl[(size_t)br * strideB + ac];
        pBl[1] = *(const uint4*)&Bl[(size_t)(br + 64) * strideB + ac];
    }

    #pragma unroll 1
    for (int s = 0; s < nsub; s++) {
        __syncthreads();
        *(uint4*)&As_h[ar][ac] = pAh;
        *(uint4*)&As_l[ar][ac] = pAl;
        *(uint4*)&Bs[br][ac]      = pBh[0];
        *(uint4*)&Bs[br + 64][ac] = pBh[1];
        __syncthreads();

        if (s + 1 < nsub) {
            const int kn = (s + 1) << 6;
            pAh = *(const uint4*)&Ah[(size_t)ar * strideA + kn + ac];
            pAl = *(const uint4*)&Al[(size_t)ar * strideA + kn + ac];
            pBh[0] = *(const uint4*)&Bh[(size_t)br * strideB + kn + ac];
            pBh[1] = *(const uint4*)&Bh[(size_t)(br + 64) * strideB + kn + ac];
        }

        unsigned Afh[4][4], Afl[4][4];
        #pragma unroll
        for (int kst = 0; kst < 4; kst++) {
            unsigned off = ((m0w + lrow) * 72 + (kst << 4) + lcol) << 1;
            ldsm4v(Afh[kst], sAh + off);
            ldsm4v(Afl[kst], sAl + off);
        }
        #pragma unroll
        for (int kst = 0; kst < 4; kst++) {
            #pragma unroll
            for (int ng = 0; ng < 2; ng++) {
                unsigned r[4];
                unsigned off = ((n0w + (ng << 4) + lrow) * 72 + (kst << 4) + lcol) << 1;
                ldsm4v(r, sB + off);
                mma16816(acc[2*ng],   Afh[kst], r[0], r[2]);
                mma16816(acc[2*ng+1], Afh[kst], r[1], r[3]);
                mma16816(acc[2*ng],   Afl[kst], r[0], r[2]);
                mma16816(acc[2*ng+1], Afl[kst], r[1], r[3]);
            }
        }
        if (THREE) {
            __syncthreads();
            *(uint4*)&Bs[br][ac]      = pBl[0];
            *(uint4*)&Bs[br + 64][ac] = pBl[1];
            __syncthreads();
            if (s + 1 < nsub) {
                const int kn = (s + 1) << 6;
                pBl[0] = *(const uint4*)&Bl[(size_t)br * strideB + kn + ac];
                pBl[1] = *(const uint4*)&Bl[(size_t)(br + 64) * strideB + kn + ac];
            }
            #pragma unroll
            for (int kst = 0; kst < 4; kst++) {
                #pragma unroll
                for (int ng = 0; ng < 2; ng++) {
                    unsigned r[4];
                    unsigned off = ((n0w + (ng << 4) + lrow) * 72 + (kst << 4) + lcol) << 1;
                    ldsm4v(r, sB + off);
                    mma16816(acc[2*ng],   Afh[kst], r[0], r[2]);
                    mma16816(acc[2*ng+1], Afh[kst], r[1], r[3]);
                }
            }
        }
    }

    const int g  = lane >> 2;
    const int tg = lane & 3;
    #pragma unroll
    for (int f = 0; f < 4; f++) {
        int coloff = n0w + (f << 3) + (tg << 1);
        int row0   = m0w + g;
        *(float2*)&outBase[(size_t)row0 * strideO + coloff] =
            make_float2(acc[f][0], acc[f][1]);
        *(float2*)&outBase[(size_t)(row0 + 8) * strideO + coloff] =
            make_float2(acc[f][2], acc[f][3]);
    }
}

// ---------------------------------------------------------------------------
// One-time splits.
// ---------------------------------------------------------------------------
__global__ void __launch_bounds__(256) split_transpose_kernel(
    const float* __restrict__ W, int Kdim, int Ndim, int mode)
{
    __shared__ float tile[64][65];
    __nv_bfloat16* outH = mode ? g_WiTh : g_WhT;
    __nv_bfloat16* outL = mode ? g_WiTl : g_WlT;
    const int k0 = blockIdx.y * 64, n0 = blockIdx.x * 64;
    const int tid = threadIdx.x;
    #pragma unroll
    for (int i = 0; i < 16; i++) {
        int idx = tid + (i << 8);
        int r = idx >> 6, c = idx & 63;
        tile[r][c] = W[(size_t)(k0 + r) * Ndim + n0 + c];
    }
    __syncthreads();
    #pragma unroll
    for (int i = 0; i < 16; i++) {
        int idx = tid + (i << 8);
        int nn = idx >> 6, kk = idx & 63;
        float w = tile[kk][nn];
        __nv_bfloat16 h = __float2bfloat16(w);
        outH[(size_t)(n0 + nn) * Kdim + (k0 + kk)] = h;
        outL[(size_t)(n0 + nn) * Kdim + (k0 + kk)] =
            __float2bfloat16(w - __bfloat162float(h));
    }
}

__global__ void __launch_bounds__(256) split_x_kernel(const float* __restrict__ x)
{
    size_t i = (size_t)blockIdx.x * 256 + threadIdx.x;
    float v = x[i];
    __nv_bfloat16 h = __float2bfloat16(v);
    g_Xh[i] = h;
    g_Xl[i] = __float2bfloat16(v - __bfloat162float(h));
}

// ---------------------------------------------------------------------------
// Precompute U = x @ W_input (3-term). grid (16, 512), 512 threads.
// ---------------------------------------------------------------------------
__global__ void __launch_bounds__(PTHREADS) precompute_u_mma()
{
    __shared__ __align__(16) __nv_bfloat16 As_h[64][72];
    __shared__ __align__(16) __nv_bfloat16 As_l[64][72];
    __shared__ __align__(16) __nv_bfloat16 Bs[128][72];
    const int t = blockIdx.y, n0 = blockIdx.x * 128, tid = threadIdx.x;
    mma_tile_64x128_w16<true>(g_Xh + (size_t)t * EDIM, g_Xl + (size_t)t * EDIM,
                              (size_t)RSTEPS * EDIM,
                              g_WiTh + (size_t)n0 * EDIM, g_WiTl + (size_t)n0 * EDIM,
                              EDIM, EDIM / 64,
                              g_U + (size_t)t * BATCH * REC + n0, REC,
                              As_h, As_l, Bs, tid);
}

// ---------------------------------------------------------------------------
// Warp-parallel bucket select (proven).
// ---------------------------------------------------------------------------
__device__ __forceinline__ void bucket_select(
    unsigned* hist, unsigned* sh_prefix, unsigned* sh_k, int shift, int tid)
{
    if (tid < 32) {
        unsigned h[8], lsum = 0;
        int base = tid << 3;
        #pragma unroll
        for (int i = 0; i < 8; i++) { h[i] = hist[base + i]; lsum += h[i]; }
        unsigned inc = lsum;
        #pragma unroll
        for (int off = 16; off > 0; off >>= 1) {
            unsigned v = __shfl_down_sync(0xFFFFFFFFu, inc, off);
            if (tid + off < 32) inc += v;
        }
        unsigned k = *sh_k;
        unsigned above = inc - lsum;
        if (inc >= k && above < k) {
            unsigned S = above;
            #pragma unroll
            for (int i = 7; i >= 0; i--) {
                S += h[i];
                if (S >= k) {
                    *sh_k = k - (S - h[i]);
                    *sh_prefix |= ((unsigned)(base + i) << shift);
                    break;
                }
            }
        }
    }
}

// ---------------------------------------------------------------------------
__device__ __forceinline__ void grid_barrier(unsigned target) {
    __syncthreads();
    if (threadIdx.x == 0) {
        __threadfence();
        atomicAdd(&g_bar, 1u);
        while (*(volatile unsigned*)&g_bar < target) { }
        __threadfence();
    }
    __syncthreads();
}

// ---------------------------------------------------------------------------
// Persistent scan, 512 threads. Phase A: 2-term MMA tile (16 warps).
// Phase B: 4 elements/thread — vector gather + radix select + tanh + norm.
// ---------------------------------------------------------------------------
__global__ void __launch_bounds__(PTHREADS) persist_kernel(float* __restrict__ out)
{
    __shared__ __align__(16) __nv_bfloat16 As_h[64][72];
    __shared__ __align__(16) __nv_bfloat16 As_l[64][72];
    __shared__ __align__(16) __nv_bfloat16 Bs[128][72];
    __shared__ unsigned hist[256];
    __shared__ unsigned sh_prefix, sh_k;
    __shared__ float red[16];

    const int bid = blockIdx.x;
    const int tid = threadIdx.x;

    for (int i = bid * PTHREADS + tid; i < BATCH * REC; i += GRID * PTHREADS) {
        g_Rh[i] = __float2bfloat16(0.0f);
        g_Rl[i] = __float2bfloat16(0.0f);
    }
    unsigned baridx = 1;
    grid_barrier(baridx * GRID);

    const int ntile = bid & 15;
    const int kc    = bid >> 4;
    const int n0    = ntile * 128;
    const int kbase = kc * 256;
    const int m     = bid;

    for (int step = 0; step < RSTEPS; step++) {
        // ================= phase A (2-term) =================
        mma_tile_64x128_w16<false>(g_Rh + kbase, g_Rl + kbase, REC,
                                   g_WhT + (size_t)n0 * REC + kbase,
                                   (const __nv_bfloat16*)nullptr,
                                   REC, 4,
                                   g_part + (size_t)kc * BATCH * REC + n0, REC,
                                   As_h, As_l, Bs, tid);
        baridx++;
        grid_barrier(baridx * GRID);

        // ================= phase B =================
        if (bid < BATCH) {
            float zv[4], uv[4];
            if (tid < 256) hist[tid] = 0u;
            if (tid == 0) { sh_prefix = 0u; sh_k = KTOP; }
            __syncthreads();
            const int j4 = tid << 2;
            {
                float4 a = make_float4(0.f, 0.f, 0.f, 0.f);
                #pragma unroll
                for (int c = 0; c < 8; c++) {
                    float4 p = *(const float4*)&g_part[((size_t)c * BATCH + m) * REC + j4];
                    a.x += p.x; a.y += p.y; a.z += p.z; a.w += p.w;
                }
                zv[0] = a.x; zv[1] = a.y; zv[2] = a.z; zv[3] = a.w;
                float4 u4 = *(const float4*)&g_U[((size_t)step * BATCH + m) * REC + j4];
                uv[0] = u4.x; uv[1] = u4.y; uv[2] = u4.z; uv[3] = u4.w;
                atomicAdd(&hist[keyOf(a.x) >> 24], 1u);
                atomicAdd(&hist[keyOf(a.y) >> 24], 1u);
                atomicAdd(&hist[keyOf(a.z) >> 24], 1u);
                atomicAdd(&hist[keyOf(a.w) >> 24], 1u);
            }
            __syncthreads();
            bucket_select(hist, &sh_prefix, &sh_k, 24, tid);
            __syncthreads();
            #pragma unroll
            for (int pi = 0; pi < 3; pi++) {
                const int shift = 16 - (pi << 3);
                if (tid < 256) hist[tid] = 0u;
                __syncthreads();
                unsigned prefix = sh_prefix;
                unsigned maskH  = 0xFFFFFFFFu << (shift + 8);
                #pragma unroll
                for (int jj = 0; jj < 4; jj++) {
                    unsigned key = keyOf(zv[jj]);
                    if (((key ^ prefix) & maskH) == 0u)
                        atomicAdd(&hist[(key >> shift) & 0xFFu], 1u);
                }
                __syncthreads();
                bucket_select(hist, &sh_prefix, &sh_k, shift, tid);
                __syncthreads();
            }
            const unsigned thKey = sh_prefix;

            float part = 0.0f;
            #pragma unroll
            for (int jj = 0; jj < 4; jj++) {
                float zz = zv[jj];
                float sv = (keyOf(zz) >= thKey) ? zz : 0.0f;
                float v  = ftanh(uv[jj] + sv);
                zv[jj]   = v;
                part += v * v;
            }
            #pragma unroll
            for (int o = 16; o > 0; o >>= 1)
                part += __shfl_down_sync(0xFFFFFFFFu, part, o);
            if ((tid & 31) == 0) red[tid >> 5] = part;
            __syncthreads();
            if (tid < 32) {
                float v = (tid < 16) ? red[tid] : 0.0f;
                #pragma unroll
                for (int o = 8; o > 0; o >>= 1)
                    v += __shfl_down_sync(0xFFFFFFFFu, v, o);
                if (tid == 0) red[0] = v;
            }
            __syncthreads();
            const float inv = 1.0f / (sqrtf(red[0]) + 1e-6f);
            {
                float v0 = zv[0] * inv, v1 = zv[1] * inv;
                float v2 = zv[2] * inv, v3 = zv[3] * inv;
                __nv_bfloat16 h0 = __float2bfloat16(v0), h1 = __float2bfloat16(v1);
                __nv_bfloat16 h2 = __float2bfloat16(v2), h3 = __float2bfloat16(v3);
                __nv_bfloat16 l0 = __float2bfloat16(v0 - __bfloat162float(h0));
                __nv_bfloat16 l1 = __float2bfloat16(v1 - __bfloat162float(h1));
                __nv_bfloat16 l2 = __float2bfloat16(v2 - __bfloat162float(h2));
                __nv_bfloat16 l3 = __float2bfloat16(v3 - __bfloat162float(h3));
                __nv_bfloat162 hp0, hp1, lp0, lp1;
                hp0.x = h0; hp0.y = h1; hp1.x = h2; hp1.y = h3;
                lp0.x = l0; lp0.y = l1; lp1.x = l2; lp1.y = l3;
                *(__nv_bfloat162*)&g_Rh[(size_t)m * REC + j4]     = hp0;
                *(__nv_bfloat162*)&g_Rh[(size_t)m * REC + j4 + 2] = hp1;
                *(__nv_bfloat162*)&g_Rl[(size_t)m * REC + j4]     = lp0;
                *(__nv_bfloat162*)&g_Rl[(size_t)m * REC + j4 + 2] = lp1;
                if (step == RSTEPS - 1)
                    *(float4*)&out[(size_t)m * REC + j4] = make_float4(v0, v1, v2, v3);
            }
        }
        baridx++;
        if (step < RSTEPS - 1) {
            grid_barrier(baridx * GRID);
        } else {
            __syncthreads();
            if (tid == 0) {
                __threadfence();
                unsigned p = atomicAdd(&g_bar, 1u);
                if (p == (unsigned)NBAR * GRID - 1u) atomicExch(&g_bar, 0u);
            }
        }
    }
}

// ---------------------------------------------------------------------------
extern "C" void kernel_launch(void* const* d_in, const int* in_sizes, int n_in,
                              void* d_out, int out_size)
{
    const float* x  = nullptr;   // 64*512*512  = 16777216
    const float* Wi = nullptr;   // 512*2048    = 1048576
    const float* Wr = nullptr;   // 2048*2048   = 4194304
    for (int i = 0; i < n_in; i++) {
        if      (in_sizes[i] == BATCH * RSTEPS * EDIM) x  = (const float*)d_in[i];
        else if (in_sizes[i] == EDIM * REC)            Wi = (const float*)d_in[i];
        else if (in_sizes[i] == REC * REC)             Wr = (const float*)d_in[i];
    }
    float* out = (float*)d_out;

    split_transpose_kernel<<<dim3(REC / 64, REC / 64), 256>>>(Wr, REC, REC, 0);
    split_transpose_kernel<<<dim3(REC / 64, EDIM / 64), 256>>>(Wi, EDIM, REC, 1);
    split_x_kernel<<<(BATCH * RSTEPS * EDIM) / 256, 256>>>(x);
    precompute_u_mma<<<dim3(REC / 128, RSTEPS), PTHREADS>>>();
    persist_kernel<<<GRID, PTHREADS>>>(out);
}

// round 13
// speedup vs baseline: 1.1770x; 1.1770x over previous
#include <cuda_runtime.h>
#include <cuda_bf16.h>

#define REC      2048
#define BATCH    64
#define RSTEPS   512
#define EDIM     512
#define KTOP     819
#define GRID     128
#define PTHREADS 256
#define NBAR     (1 + 2*RSTEPS)

// ---- static device scratch ----
__device__ __nv_bfloat16 g_Rh[BATCH * REC];               // r (bf16, single-term state)
__device__ __nv_bfloat16 g_WhT[(size_t)REC * REC];        // Wr hi, [n][k]
__device__ __nv_bfloat16 g_WlT[(size_t)REC * REC];        // Wr lo, [n][k] (split kernel writes; unused by persist)
__device__ __nv_bfloat16 g_WiTh[(size_t)REC * EDIM];      // Wi hi, [n][k]
__device__ __nv_bfloat16 g_WiTl[(size_t)REC * EDIM];      // Wi lo, [n][k]
__device__ __nv_bfloat16 g_Xh[(size_t)BATCH * RSTEPS * EDIM];
__device__ __nv_bfloat16 g_Xl[(size_t)BATCH * RSTEPS * EDIM];
__device__ float g_part[8 * BATCH * REC];
__device__ float g_U[(size_t)RSTEPS * BATCH * REC];
__device__ unsigned g_bar;

__device__ __forceinline__ unsigned keyOf(float f) {
    unsigned b = __float_as_uint(f);
    return (b & 0x80000000u) ? ~b : (b | 0x80000000u);
}
__device__ __forceinline__ float ftanh(float x) {
    float t = __expf(2.0f * x);
    return 1.0f - __fdividef(2.0f, t + 1.0f);
}

// ---- tensor-core primitives (proven) ----
__device__ __forceinline__ void ldsm4v(unsigned* r, unsigned addr) {
    asm volatile("ldmatrix.sync.aligned.m8n8.x4.shared.b16 {%0,%1,%2,%3}, [%4];"
                 : "=r"(r[0]), "=r"(r[1]), "=r"(r[2]), "=r"(r[3]) : "r"(addr));
}
__device__ __forceinline__ void mma16816(float* d, const unsigned* a,
                                         unsigned b0, unsigned b1) {
    asm volatile("mma.sync.aligned.m16n8k16.row.col.f32.bf16.bf16.f32 "
                 "{%0,%1,%2,%3}, {%4,%5,%6,%7}, {%8,%9}, {%0,%1,%2,%3};"
                 : "+f"(d[0]), "+f"(d[1]), "+f"(d[2]), "+f"(d[3])
                 : "r"(a[0]), "r"(a[1]), "r"(a[2]), "r"(a[3]), "r"(b0), "r"(b1));
}

// ---------------------------------------------------------------------------
// 3-term tile (precompute): out = Ah@Bh + Al@Bh + Ah@Bl.
// 256 threads, 8 warps (4M x 2N). R11-proven byte-for-byte.
// ---------------------------------------------------------------------------
__device__ __forceinline__ void mma_tile_3term(
    const __nv_bfloat16* __restrict__ Ah, const __nv_bfloat16* __restrict__ Al,
    size_t strideA,
    const __nv_bfloat16* __restrict__ Bh, const __nv_bfloat16* __restrict__ Bl,
    size_t strideB,
    int nsub,
    float* __restrict__ outBase, size_t strideO,
    __nv_bfloat16 (*As_h)[72], __nv_bfloat16 (*As_l)[72], __nv_bfloat16 (*Bs)[72],
    int tid)
{
    const int lane = tid & 31, wid = tid >> 5;
    const int m0w = (wid & 3) << 4;
    const int n0w = (wid >> 2) << 6;
    const unsigned sAh = (unsigned)__cvta_generic_to_shared(&As_h[0][0]);
    const unsigned sAl = (unsigned)__cvta_generic_to_shared(&As_l[0][0]);
    const unsigned sB  = (unsigned)__cvta_generic_to_shared(&Bs[0][0]);
    const unsigned lrow = (lane & 15);
    const unsigned lcol = (lane >> 4) << 3;

    const int ar0 = tid >> 3, ac0 = (tid & 7) << 3;
    const int ar1 = (tid + 256) >> 3;
    const int br0 = tid >> 3;

    float acc[8][4];
    #pragma unroll
    for (int f = 0; f < 8; f++)
        #pragma unroll
        for (int q = 0; q < 4; q++) acc[f][q] = 0.0f;

    uint4 pAh[2], pAl[2], pBh[4], pBl[4];
    pAh[0] = *(const uint4*)&Ah[(size_t)ar0 * strideA + ac0];
    pAl[0] = *(const uint4*)&Al[(size_t)ar0 * strideA + ac0];
    pAh[1] = *(const uint4*)&Ah[(size_t)ar1 * strideA + ac0];
    pAl[1] = *(const uint4*)&Al[(size_t)ar1 * strideA + ac0];
    #pragma unroll
    for (int i = 0; i < 4; i++) {
        pBh[i] = *(const uint4*)&Bh[(size_t)(br0 + (i << 5)) * strideB + ac0];
        pBl[i] = *(const uint4*)&Bl[(size_t)(br0 + (i << 5)) * strideB + ac0];
    }

    #pragma unroll 1
    for (int s = 0; s < nsub; s++) {
        __syncthreads();
        *(uint4*)&As_h[ar0][ac0] = pAh[0];
        *(uint4*)&As_l[ar0][ac0] = pAl[0];
        *(uint4*)&As_h[ar1][ac0] = pAh[1];
        *(uint4*)&As_l[ar1][ac0] = pAl[1];
        #pragma unroll
        for (int i = 0; i < 4; i++)
            *(uint4*)&Bs[br0 + (i << 5)][ac0] = pBh[i];
        __syncthreads();

        if (s + 1 < nsub) {
            const int kn = (s + 1) << 6;
            pAh[0] = *(const uint4*)&Ah[(size_t)ar0 * strideA + kn + ac0];
            pAl[0] = *(const uint4*)&Al[(size_t)ar0 * strideA + kn + ac0];
            pAh[1] = *(const uint4*)&Ah[(size_t)ar1 * strideA + kn + ac0];
            pAl[1] = *(const uint4*)&Al[(size_t)ar1 * strideA + kn + ac0];
            #pragma unroll
            for (int i = 0; i < 4; i++)
                pBh[i] = *(const uint4*)&Bh[(size_t)(br0 + (i << 5)) * strideB + kn + ac0];
        }

        unsigned Afh[4][4], Afl[4][4];
        #pragma unroll
        for (int kst = 0; kst < 4; kst++) {
            unsigned off = ((m0w + lrow) * 72 + (kst << 4) + lcol) << 1;
            ldsm4v(Afh[kst], sAh + off);
            ldsm4v(Afl[kst], sAl + off);
        }
        #pragma unroll
        for (int kst = 0; kst < 4; kst++) {
            #pragma unroll
            for (int ng = 0; ng < 4; ng++) {
                unsigned r[4];
                unsigned off = ((n0w + (ng << 4) + lrow) * 72 + (kst << 4) + lcol) << 1;
                ldsm4v(r, sB + off);
                mma16816(acc[2*ng],   Afh[kst], r[0], r[2]);
                mma16816(acc[2*ng+1], Afh[kst], r[1], r[3]);
                mma16816(acc[2*ng],   Afl[kst], r[0], r[2]);
                mma16816(acc[2*ng+1], Afl[kst], r[1], r[3]);
            }
        }
        __syncthreads();
        #pragma unroll
        for (int i = 0; i < 4; i++)
            *(uint4*)&Bs[br0 + (i << 5)][ac0] = pBl[i];
        __syncthreads();
        if (s + 1 < nsub) {
            const int kn = (s + 1) << 6;
            #pragma unroll
            for (int i = 0; i < 4; i++)
                pBl[i] = *(const uint4*)&Bl[(size_t)(br0 + (i << 5)) * strideB + kn + ac0];
        }
        #pragma unroll
        for (int kst = 0; kst < 4; kst++) {
            #pragma unroll
            for (int ng = 0; ng < 4; ng++) {
                unsigned r[4];
                unsigned off = ((n0w + (ng << 4) + lrow) * 72 + (kst << 4) + lcol) << 1;
                ldsm4v(r, sB + off);
                mma16816(acc[2*ng],   Afh[kst], r[0], r[2]);
                mma16816(acc[2*ng+1], Afh[kst], r[1], r[3]);
            }
        }
    }

    const int g  = lane >> 2;
    const int tg = lane & 3;
    #pragma unroll
    for (int f = 0; f < 8; f++) {
        int coloff = n0w + (f << 3) + (tg << 1);
        int row0   = m0w + g;
        *(float2*)&outBase[(size_t)row0 * strideO + coloff] =
            make_float2(acc[f][0], acc[f][1]);
        *(float2*)&outBase[(size_t)(row0 + 8) * strideO + coloff] =
            make_float2(acc[f][2], acc[f][3]);
    }
}

// ---------------------------------------------------------------------------
// 1-term tile (persist): out = Ah@Bh. Same fragment addressing, Al removed.
// ---------------------------------------------------------------------------
__device__ __forceinline__ void mma_tile_1term(
    const __nv_bfloat16* __restrict__ Ah, size_t strideA,
    const __nv_bfloat16* __restrict__ Bh, size_t strideB,
    int nsub,
    float* __restrict__ outBase, size_t strideO,
    __nv_bfloat16 (*As_h)[72], __nv_bfloat16 (*Bs)[72],
    int tid)
{
    const int lane = tid & 31, wid = tid >> 5;
    const int m0w = (wid & 3) << 4;
    const int n0w = (wid >> 2) << 6;
    const unsigned sAh = (unsigned)__cvta_generic_to_shared(&As_h[0][0]);
    const unsigned sB  = (unsigned)__cvta_generic_to_shared(&Bs[0][0]);
    const unsigned lrow = (lane & 15);
    const unsigned lcol = (lane >> 4) << 3;

    const int ar0 = tid >> 3, ac0 = (tid & 7) << 3;
    const int ar1 = (tid + 256) >> 3;
    const int br0 = tid >> 3;

    float acc[8][4];
    #pragma unroll
    for (int f = 0; f < 8; f++)
        #pragma unroll
        for (int q = 0; q < 4; q++) acc[f][q] = 0.0f;

    uint4 pAh[2], pBh[4];
    pAh[0] = *(const uint4*)&Ah[(size_t)ar0 * strideA + ac0];
    pAh[1] = *(const uint4*)&Ah[(size_t)ar1 * strideA + ac0];
    #pragma unroll
    for (int i = 0; i < 4; i++)
        pBh[i] = *(const uint4*)&Bh[(size_t)(br0 + (i << 5)) * strideB + ac0];

    #pragma unroll 1
    for (int s = 0; s < nsub; s++) {
        __syncthreads();
        *(uint4*)&As_h[ar0][ac0] = pAh[0];
        *(uint4*)&As_h[ar1][ac0] = pAh[1];
        #pragma unroll
        for (int i = 0; i < 4; i++)
            *(uint4*)&Bs[br0 + (i << 5)][ac0] = pBh[i];
        __syncthreads();

        if (s + 1 < nsub) {
            const int kn = (s + 1) << 6;
            pAh[0] = *(const uint4*)&Ah[(size_t)ar0 * strideA + kn + ac0];
            pAh[1] = *(const uint4*)&Ah[(size_t)ar1 * strideA + kn + ac0];
            #pragma unroll
            for (int i = 0; i < 4; i++)
                pBh[i] = *(const uint4*)&Bh[(size_t)(br0 + (i << 5)) * strideB + kn + ac0];
        }

        unsigned Af[4][4];
        #pragma unroll
        for (int kst = 0; kst < 4; kst++) {
            unsigned off = ((m0w + lrow) * 72 + (kst << 4) + lcol) << 1;
            ldsm4v(Af[kst], sAh + off);
        }
        #pragma unroll
        for (int kst = 0; kst < 4; kst++) {
            #pragma unroll
            for (int ng = 0; ng < 4; ng++) {
                unsigned r[4];
                unsigned off = ((n0w + (ng << 4) + lrow) * 72 + (kst << 4) + lcol) << 1;
                ldsm4v(r, sB + off);
                mma16816(acc[2*ng],   Af[kst], r[0], r[2]);
                mma16816(acc[2*ng+1], Af[kst], r[1], r[3]);
            }
        }
    }

    const int g  = lane >> 2;
    const int tg = lane & 3;
    #pragma unroll
    for (int f = 0; f < 8; f++) {
        int coloff = n0w + (f << 3) + (tg << 1);
        int row0   = m0w + g;
        *(float2*)&outBase[(size_t)row0 * strideO + coloff] =
            make_float2(acc[f][0], acc[f][1]);
        *(float2*)&outBase[(size_t)(row0 + 8) * strideO + coloff] =
            make_float2(acc[f][2], acc[f][3]);
    }
}

// ---------------------------------------------------------------------------
// One-time splits.
// ---------------------------------------------------------------------------
__global__ void __launch_bounds__(256) split_transpose_kernel(
    const float* __restrict__ W, int Kdim, int Ndim, int mode)
{
    __shared__ float tile[64][65];
    __nv_bfloat16* outH = mode ? g_WiTh : g_WhT;
    __nv_bfloat16* outL = mode ? g_WiTl : g_WlT;
    const int k0 = blockIdx.y * 64, n0 = blockIdx.x * 64;
    const int tid = threadIdx.x;
    #pragma unroll
    for (int i = 0; i < 16; i++) {
        int idx = tid + (i << 8);
        int r = idx >> 6, c = idx & 63;
        tile[r][c] = W[(size_t)(k0 + r) * Ndim + n0 + c];
    }
    __syncthreads();
    #pragma unroll
    for (int i = 0; i < 16; i++) {
        int idx = tid + (i << 8);
        int nn = idx >> 6, kk = idx & 63;
        float w = tile[kk][nn];
        __nv_bfloat16 h = __float2bfloat16(w);
        outH[(size_t)(n0 + nn) * Kdim + (k0 + kk)] = h;
        outL[(size_t)(n0 + nn) * Kdim + (k0 + kk)] =
            __float2bfloat16(w - __bfloat162float(h));
    }
}

__global__ void __launch_bounds__(256) split_x_kernel(const float* __restrict__ x)
{
    size_t i = (size_t)blockIdx.x * 256 + threadIdx.x;
    float v = x[i];
    __nv_bfloat16 h = __float2bfloat16(v);
    g_Xh[i] = h;
    g_Xl[i] = __float2bfloat16(v - __bfloat162float(h));
}

// ---------------------------------------------------------------------------
// Precompute U = x @ W_input (3-term; precision anchor). grid (16, 512).
// ---------------------------------------------------------------------------
__global__ void __launch_bounds__(256) precompute_u_mma()
{
    __shared__ __align__(16) __nv_bfloat16 As_h[64][72];
    __shared__ __align__(16) __nv_bfloat16 As_l[64][72];
    __shared__ __align__(16) __nv_bfloat16 Bs[128][72];
    const int t = blockIdx.y, n0 = blockIdx.x * 128, tid = threadIdx.x;
    mma_tile_3term(g_Xh + (size_t)t * EDIM, g_Xl + (size_t)t * EDIM,
                   (size_t)RSTEPS * EDIM,
                   g_WiTh + (size_t)n0 * EDIM, g_WiTl + (size_t)n0 * EDIM,
                   EDIM, EDIM / 64,
                   g_U + (size_t)t * BATCH * REC + n0, REC,
                   As_h, As_l, Bs, tid);
}

// ---------------------------------------------------------------------------
// Warp-parallel bucket select (proven).
// ---------------------------------------------------------------------------
__device__ __forceinline__ void bucket_select(
    unsigned* hist, unsigned* sh_prefix, unsigned* sh_k, int shift, int tid)
{
    if (tid < 32) {
        unsigned h[8], lsum = 0;
        int base = tid << 3;
        #pragma unroll
        for (int i = 0; i < 8; i++) { h[i] = hist[base + i]; lsum += h[i]; }
        unsigned inc = lsum;
        #pragma unroll
        for (int off = 16; off > 0; off >>= 1) {
            unsigned v = __shfl_down_sync(0xFFFFFFFFu, inc, off);
            if (tid + off < 32) inc += v;
        }
        unsigned k = *sh_k;
        unsigned above = inc - lsum;
        if (inc >= k && above < k) {
            unsigned S = above;
            #pragma unroll
            for (int i = 7; i >= 0; i--) {
                S += h[i];
                if (S >= k) {
                    *sh_k = k - (S - h[i]);
                    *sh_prefix |= ((unsigned)(base + i) << shift);
                    break;
                }
            }
        }
    }
}

// ---------------------------------------------------------------------------
__device__ __forceinline__ void grid_barrier(unsigned target) {
    __syncthreads();
    if (threadIdx.x == 0) {
        __threadfence();
        atomicAdd(&g_bar, 1u);
        while (*(volatile unsigned*)&g_bar < target) { }
        __threadfence();
    }
    __syncthreads();
}

// ---------------------------------------------------------------------------
// Persistent scan, 256 threads. Phase A: 1-term MMA tile (z = rh@Wh).
// Phase B: 8 elements/thread — vector gather + radix select + tanh + norm.
// ---------------------------------------------------------------------------
__global__ void __launch_bounds__(PTHREADS) persist_kernel(float* __restrict__ out)
{
    __shared__ __align__(16) __nv_bfloat16 As_h[64][72];
    __shared__ __align__(16) __nv_bfloat16 Bs[128][72];
    __shared__ unsigned hist[256];
    __shared__ unsigned sh_prefix, sh_k;
    __shared__ float red[8];

    const int bid = blockIdx.x;
    const int tid = threadIdx.x;

    for (int i = bid * PTHREADS + tid; i < BATCH * REC; i += GRID * PTHREADS)
        g_Rh[i] = __float2bfloat16(0.0f);
    unsigned baridx = 1;
    grid_barrier(baridx * GRID);

    const int ntile = bid & 15;
    const int kc    = bid >> 4;
    const int n0    = ntile * 128;
    const int kbase = kc * 256;
    const int m     = bid;

    for (int step = 0; step < RSTEPS; step++) {
        // ================= phase A (1-term) =================
        mma_tile_1term(g_Rh + kbase, REC,
                       g_WhT + (size_t)n0 * REC + kbase, REC, 4,
                       g_part + (size_t)kc * BATCH * REC + n0, REC,
                       As_h, Bs, tid);
        baridx++;
        grid_barrier(baridx * GRID);

        // ================= phase B =================
        if (bid < BATCH) {
            float zv[8], uv[8];
            hist[tid] = 0u;
            if (tid == 0) { sh_prefix = 0u; sh_k = KTOP; }
            __syncthreads();
            #pragma unroll
            for (int g2 = 0; g2 < 2; g2++) {
                const int j4 = (tid << 2) + (g2 << 10);
                float4 a = make_float4(0.f, 0.f, 0.f, 0.f);
                #pragma unroll
                for (int c = 0; c < 8; c++) {
                    float4 p = *(const float4*)&g_part[((size_t)c * BATCH + m) * REC + j4];
                    a.x += p.x; a.y += p.y; a.z += p.z; a.w += p.w;
                }
                zv[g2*4+0] = a.x; zv[g2*4+1] = a.y; zv[g2*4+2] = a.z; zv[g2*4+3] = a.w;
                float4 u4 = *(const float4*)&g_U[((size_t)step * BATCH + m) * REC + j4];
                uv[g2*4+0] = u4.x; uv[g2*4+1] = u4.y; uv[g2*4+2] = u4.z; uv[g2*4+3] = u4.w;
                atomicAdd(&hist[keyOf(a.x) >> 24], 1u);
                atomicAdd(&hist[keyOf(a.y) >> 24], 1u);
                atomicAdd(&hist[keyOf(a.z) >> 24], 1u);
                atomicAdd(&hist[keyOf(a.w) >> 24], 1u);
            }
            __syncthreads();
            bucket_select(hist, &sh_prefix, &sh_k, 24, tid);
            __syncthreads();
            #pragma unroll
            for (int pi = 0; pi < 3; pi++) {
                const int shift = 16 - (pi << 3);
                hist[tid] = 0u;
                __syncthreads();
                unsigned prefix = sh_prefix;
                unsigned maskH  = 0xFFFFFFFFu << (shift + 8);
                #pragma unroll
                for (int jj = 0; jj < 8; jj++) {
                    unsigned key = keyOf(zv[jj]);
                    if (((key ^ prefix) & maskH) == 0u)
                        atomicAdd(&hist[(key >> shift) & 0xFFu], 1u);
                }
                __syncthreads();
                bucket_select(hist, &sh_prefix, &sh_k, shift, tid);
                __syncthreads();
            }
            const unsigned thKey = sh_prefix;

            float part = 0.0f;
            #pragma unroll
            for (int jj = 0; jj < 8; jj++) {
                float zz = zv[jj];
                float sv = (keyOf(zz) >= thKey) ? zz : 0.0f;
                float v  = ftanh(uv[jj] + sv);
                zv[jj]   = v;
                part += v * v;
            }
            #pragma unroll
            for (int o = 16; o > 0; o >>= 1)
                part += __shfl_down_sync(0xFFFFFFFFu, part, o);
            if ((tid & 31) == 0) red[tid >> 5] = part;
            __syncthreads();
            if (tid < 32) {
                float v = (tid < 8) ? red[tid] : 0.0f;
                #pragma unroll
                for (int o = 4; o > 0; o >>= 1)
                    v += __shfl_down_sync(0xFFFFFFFFu, v, o);
                if (tid == 0) red[0] = v;
            }
            __syncthreads();
            const float inv = 1.0f / (sqrtf(red[0]) + 1e-6f);
            #pragma unroll
            for (int g2 = 0; g2 < 2; g2++) {
                const int j4 = (tid << 2) + (g2 << 10);
                float v0 = zv[g2*4+0] * inv, v1 = zv[g2*4+1] * inv;
                float v2 = zv[g2*4+2] * inv, v3 = zv[g2*4+3] * inv;
                __nv_bfloat162 hp0, hp1;
                hp0.x = __float2bfloat16(v0); hp0.y = __float2bfloat16(v1);
                hp1.x = __float2bfloat16(v2); hp1.y = __float2bfloat16(v3);
                *(__nv_bfloat162*)&g_Rh[(size_t)m * REC + j4]     = hp0;
                *(__nv_bfloat162*)&g_Rh[(size_t)m * REC + j4 + 2] = hp1;
                if (step == RSTEPS - 1)
                    *(float4*)&out[(size_t)m * REC + j4] = make_float4(v0, v1, v2, v3);
            }
        }
        baridx++;
        if (step < RSTEPS - 1) {
            grid_barrier(baridx * GRID);
        } else {
            __syncthreads();
            if (tid == 0) {
                __threadfence();
                unsigned p = atomicAdd(&g_bar, 1u);
                if (p == (unsigned)NBAR * GRID - 1u) atomicExch(&g_bar, 0u);
            }
        }
    }
}

// ---------------------------------------------------------------------------
extern "C" void kernel_launch(void* const* d_in, const int* in_sizes, int n_in,
                              void* d_out, int out_size)
{
    const float* x  = nullptr;   // 64*512*512  = 16777216
    const float* Wi = nullptr;   // 512*2048    = 1048576
    const float* Wr = nullptr;   // 2048*2048   = 4194304
    for (int i = 0; i < n_in; i++) {
        if      (in_sizes[i] == BATCH * RSTEPS * EDIM) x  = (const float*)d_in[i];
        else if (in_sizes[i] == EDIM * REC)            Wi = (const float*)d_in[i];
        else if (in_sizes[i] == REC * REC)             Wr = (const float*)d_in[i];
    }
    float* out = (float*)d_out;

    split_transpose_kernel<<<dim3(REC / 64, REC / 64), 256>>>(Wr, REC, REC, 0);
    split_transpose_kernel<<<dim3(REC / 64, EDIM / 64), 256>>>(Wi, EDIM, REC, 1);
    split_x_kernel<<<(BATCH * RSTEPS * EDIM) / 256, 256>>>(x);
    precompute_u_mma<<<dim3(REC / 128, RSTEPS), 256>>>();
    persist_kernel<<<GRID, PTHREADS>>>(out);
}

// round 14
// speedup vs baseline: 1.1852x; 1.0069x over previous
#include <cuda_runtime.h>
#include <cuda_bf16.h>

#define REC      2048
#define BATCH    64
#define RSTEPS   512
#define EDIM     512
#define KTOP     819
#define GRID     128
#define PTHREADS 256
#define NBAR     (1 + 2*RSTEPS)
#define BSTRIDE  520                        // bf16 elems per resident-B row (1040B)
#define DSMEM_BYTES (64*BSTRIDE*2 + 64*72*2)  // 66560 + 9216 = 75776

// ---- static device scratch ----
__device__ __nv_bfloat16 g_Rh[BATCH * REC];               // r (bf16 state)
__device__ __nv_bfloat16 g_WhT[(size_t)REC * REC];        // Wr hi, [n][k]
__device__ __nv_bfloat16 g_WlT[(size_t)REC * REC];        // Wr lo, [n][k] (split writes; persist unused)
__device__ __nv_bfloat16 g_WiTh[(size_t)REC * EDIM];      // Wi hi, [n][k]
__device__ __nv_bfloat16 g_WiTl[(size_t)REC * EDIM];      // Wi lo, [n][k]
__device__ __nv_bfloat16 g_Xh[(size_t)BATCH * RSTEPS * EDIM];
__device__ __nv_bfloat16 g_Xl[(size_t)BATCH * RSTEPS * EDIM];
__device__ float g_part[4 * BATCH * REC];
__device__ float g_U[(size_t)RSTEPS * BATCH * REC];
__device__ unsigned g_bar;

__device__ __forceinline__ unsigned keyOf(float f) {
    unsigned b = __float_as_uint(f);
    return (b & 0x80000000u) ? ~b : (b | 0x80000000u);
}
__device__ __forceinline__ float ftanh(float x) {
    float t = __expf(2.0f * x);
    return 1.0f - __fdividef(2.0f, t + 1.0f);
}

// ---- tensor-core primitives (proven) ----
__device__ __forceinline__ void ldsm4v(unsigned* r, unsigned addr) {
    asm volatile("ldmatrix.sync.aligned.m8n8.x4.shared.b16 {%0,%1,%2,%3}, [%4];"
                 : "=r"(r[0]), "=r"(r[1]), "=r"(r[2]), "=r"(r[3]) : "r"(addr));
}
__device__ __forceinline__ void mma16816(float* d, const unsigned* a,
                                         unsigned b0, unsigned b1) {
    asm volatile("mma.sync.aligned.m16n8k16.row.col.f32.bf16.bf16.f32 "
                 "{%0,%1,%2,%3}, {%4,%5,%6,%7}, {%8,%9}, {%0,%1,%2,%3};"
                 : "+f"(d[0]), "+f"(d[1]), "+f"(d[2]), "+f"(d[3])
                 : "r"(a[0]), "r"(a[1]), "r"(a[2]), "r"(a[3]), "r"(b0), "r"(b1));
}

// ---------------------------------------------------------------------------
// 3-term tile (precompute only): out = Ah@Bh + Al@Bh + Ah@Bl.
// 256 threads, 8 warps (4M x 2N). Proven byte-for-byte (R11/R13).
// ---------------------------------------------------------------------------
__device__ __forceinline__ void mma_tile_3term(
    const __nv_bfloat16* __restrict__ Ah, const __nv_bfloat16* __restrict__ Al,
    size_t strideA,
    const __nv_bfloat16* __restrict__ Bh, const __nv_bfloat16* __restrict__ Bl,
    size_t strideB,
    int nsub,
    float* __restrict__ outBase, size_t strideO,
    __nv_bfloat16 (*As_h)[72], __nv_bfloat16 (*As_l)[72], __nv_bfloat16 (*Bs)[72],
    int tid)
{
    const int lane = tid & 31, wid = tid >> 5;
    const int m0w = (wid & 3) << 4;
    const int n0w = (wid >> 2) << 6;
    const unsigned sAh = (unsigned)__cvta_generic_to_shared(&As_h[0][0]);
    const unsigned sAl = (unsigned)__cvta_generic_to_shared(&As_l[0][0]);
    const unsigned sB  = (unsigned)__cvta_generic_to_shared(&Bs[0][0]);
    const unsigned lrow = (lane & 15);
    const unsigned lcol = (lane >> 4) << 3;

    const int ar0 = tid >> 3, ac0 = (tid & 7) << 3;
    const int ar1 = (tid + 256) >> 3;
    const int br0 = tid >> 3;

    float acc[8][4];
    #pragma unroll
    for (int f = 0; f < 8; f++)
        #pragma unroll
        for (int q = 0; q < 4; q++) acc[f][q] = 0.0f;

    uint4 pAh[2], pAl[2], pBh[4], pBl[4];
    pAh[0] = *(const uint4*)&Ah[(size_t)ar0 * strideA + ac0];
    pAl[0] = *(const uint4*)&Al[(size_t)ar0 * strideA + ac0];
    pAh[1] = *(const uint4*)&Ah[(size_t)ar1 * strideA + ac0];
    pAl[1] = *(const uint4*)&Al[(size_t)ar1 * strideA + ac0];
    #pragma unroll
    for (int i = 0; i < 4; i++) {
        pBh[i] = *(const uint4*)&Bh[(size_t)(br0 + (i << 5)) * strideB + ac0];
        pBl[i] = *(const uint4*)&Bl[(size_t)(br0 + (i << 5)) * strideB + ac0];
    }

    #pragma unroll 1
    for (int s = 0; s < nsub; s++) {
        __syncthreads();
        *(uint4*)&As_h[ar0][ac0] = pAh[0];
        *(uint4*)&As_l[ar0][ac0] = pAl[0];
        *(uint4*)&As_h[ar1][ac0] = pAh[1];
        *(uint4*)&As_l[ar1][ac0] = pAl[1];
        #pragma unroll
        for (int i = 0; i < 4; i++)
            *(uint4*)&Bs[br0 + (i << 5)][ac0] = pBh[i];
        __syncthreads();

        if (s + 1 < nsub) {
            const int kn = (s + 1) << 6;
            pAh[0] = *(const uint4*)&Ah[(size_t)ar0 * strideA + kn + ac0];
            pAl[0] = *(const uint4*)&Al[(size_t)ar0 * strideA + kn + ac0];
            pAh[1] = *(const uint4*)&Ah[(size_t)ar1 * strideA + kn + ac0];
            pAl[1] = *(const uint4*)&Al[(size_t)ar1 * strideA + kn + ac0];
            #pragma unroll
            for (int i = 0; i < 4; i++)
                pBh[i] = *(const uint4*)&Bh[(size_t)(br0 + (i << 5)) * strideB + kn + ac0];
        }

        unsigned Afh[4][4], Afl[4][4];
        #pragma unroll
        for (int kst = 0; kst < 4; kst++) {
            unsigned off = ((m0w + lrow) * 72 + (kst << 4) + lcol) << 1;
            ldsm4v(Afh[kst], sAh + off);
            ldsm4v(Afl[kst], sAl + off);
        }
        #pragma unroll
        for (int kst = 0; kst < 4; kst++) {
            #pragma unroll
            for (int ng = 0; ng < 4; ng++) {
                unsigned r[4];
                unsigned off = ((n0w + (ng << 4) + lrow) * 72 + (kst << 4) + lcol) << 1;
                ldsm4v(r, sB + off);
                mma16816(acc[2*ng],   Afh[kst], r[0], r[2]);
                mma16816(acc[2*ng+1], Afh[kst], r[1], r[3]);
                mma16816(acc[2*ng],   Afl[kst], r[0], r[2]);
                mma16816(acc[2*ng+1], Afl[kst], r[1], r[3]);
            }
        }
        __syncthreads();
        #pragma unroll
        for (int i = 0; i < 4; i++)
            *(uint4*)&Bs[br0 + (i << 5)][ac0] = pBl[i];
        __syncthreads();
        if (s + 1 < nsub) {
            const int kn = (s + 1) << 6;
            #pragma unroll
            for (int i = 0; i < 4; i++)
                pBl[i] = *(const uint4*)&Bl[(size_t)(br0 + (i << 5)) * strideB + kn + ac0];
        }
        #pragma unroll
        for (int kst = 0; kst < 4; kst++) {
            #pragma unroll
            for (int ng = 0; ng < 4; ng++) {
                unsigned r[4];
                unsigned off = ((n0w + (ng << 4) + lrow) * 72 + (kst << 4) + lcol) << 1;
                ldsm4v(r, sB + off);
                mma16816(acc[2*ng],   Afh[kst], r[0], r[2]);
                mma16816(acc[2*ng+1], Afh[kst], r[1], r[3]);
            }
        }
    }

    const int g  = lane >> 2;
    const int tg = lane & 3;
    #pragma unroll
    for (int f = 0; f < 8; f++) {
        int coloff = n0w + (f << 3) + (tg << 1);
        int row0   = m0w + g;
        *(float2*)&outBase[(size_t)row0 * strideO + coloff] =
            make_float2(acc[f][0], acc[f][1]);
        *(float2*)&outBase[(size_t)(row0 + 8) * strideO + coloff] =
            make_float2(acc[f][2], acc[f][3]);
    }
}

// ---------------------------------------------------------------------------
// One-time splits.
// ---------------------------------------------------------------------------
__global__ void __launch_bounds__(256) split_transpose_kernel(
    const float* __restrict__ W, int Kdim, int Ndim, int mode)
{
    __shared__ float tile[64][65];
    __nv_bfloat16* outH = mode ? g_WiTh : g_WhT;
    __nv_bfloat16* outL = mode ? g_WiTl : g_WlT;
    const int k0 = blockIdx.y * 64, n0 = blockIdx.x * 64;
    const int tid = threadIdx.x;
    #pragma unroll
    for (int i = 0; i < 16; i++) {
        int idx = tid + (i << 8);
        int r = idx >> 6, c = idx & 63;
        tile[r][c] = W[(size_t)(k0 + r) * Ndim + n0 + c];
    }
    __syncthreads();
    #pragma unroll
    for (int i = 0; i < 16; i++) {
        int idx = tid + (i << 8);
        int nn = idx >> 6, kk = idx & 63;
        float w = tile[kk][nn];
        __nv_bfloat16 h = __float2bfloat16(w);
        outH[(size_t)(n0 + nn) * Kdim + (k0 + kk)] = h;
        outL[(size_t)(n0 + nn) * Kdim + (k0 + kk)] =
            __float2bfloat16(w - __bfloat162float(h));
    }
}

__global__ void __launch_bounds__(256) split_x_kernel(const float* __restrict__ x)
{
    size_t i = (size_t)blockIdx.x * 256 + threadIdx.x;
    float v = x[i];
    __nv_bfloat16 h = __float2bfloat16(v);
    g_Xh[i] = h;
    g_Xl[i] = __float2bfloat16(v - __bfloat162float(h));
}

// ---------------------------------------------------------------------------
// Precompute U = x @ W_input (3-term; precision anchor). grid (16, 512).
// ---------------------------------------------------------------------------
__global__ void __launch_bounds__(256) precompute_u_mma()
{
    __shared__ __align__(16) __nv_bfloat16 As_h[64][72];
    __shared__ __align__(16) __nv_bfloat16 As_l[64][72];
    __shared__ __align__(16) __nv_bfloat16 Bs[128][72];
    const int t = blockIdx.y, n0 = blockIdx.x * 128, tid = threadIdx.x;
    mma_tile_3term(g_Xh + (size_t)t * EDIM, g_Xl + (size_t)t * EDIM,
                   (size_t)RSTEPS * EDIM,
                   g_WiTh + (size_t)n0 * EDIM, g_WiTl + (size_t)n0 * EDIM,
                   EDIM, EDIM / 64,
                   g_U + (size_t)t * BATCH * REC + n0, REC,
                   As_h, As_l, Bs, tid);
}

// ---------------------------------------------------------------------------
// Warp-parallel bucket select (proven).
// ---------------------------------------------------------------------------
__device__ __forceinline__ void bucket_select(
    unsigned* hist, unsigned* sh_prefix, unsigned* sh_k, int shift, int tid)
{
    if (tid < 32) {
        unsigned h[8], lsum = 0;
        int base = tid << 3;
        #pragma unroll
        for (int i = 0; i < 8; i++) { h[i] = hist[base + i]; lsum += h[i]; }
        unsigned inc = lsum;
        #pragma unroll
        for (int off = 16; off > 0; off >>= 1) {
            unsigned v = __shfl_down_sync(0xFFFFFFFFu, inc, off);
            if (tid + off < 32) inc += v;
        }
        unsigned k = *sh_k;
        unsigned above = inc - lsum;
        if (inc >= k && above < k) {
            unsigned S = above;
            #pragma unroll
            for (int i = 7; i >= 0; i--) {
                S += h[i];
                if (S >= k) {
                    *sh_k = k - (S - h[i]);
                    *sh_prefix |= ((unsigned)(base + i) << shift);
                    break;
                }
            }
        }
    }
}

// ---------------------------------------------------------------------------
__device__ __forceinline__ void grid_barrier(unsigned target) {
    __syncthreads();
    if (threadIdx.x == 0) {
        __threadfence();
        atomicAdd(&g_bar, 1u);
        while (*(volatile unsigned*)&g_bar < target) { }
        __threadfence();
    }
    __syncthreads();
}

// ---------------------------------------------------------------------------
// Persistent scan, 256 threads, 75 KB dynamic smem.
// Block bid: ntile = bid&31 (64 N-cols), kc = bid>>5 (512 K).
// Resident B: WhT slice [64 x 512] bf16 pinned in smem for all 512 steps.
// Phase A: z-tile = rh @ Wh (1-term), A staged per-64K-sub with prefetch.
// Phase B (blocks 0..63): 4-chunk gather + radix select + tanh + norm.
// ---------------------------------------------------------------------------
__global__ void __launch_bounds__(PTHREADS) persist_kernel(float* __restrict__ out)
{
    extern __shared__ __align__(16) char dsm[];
    __nv_bfloat16* Bs = (__nv_bfloat16*)dsm;                  // [64][BSTRIDE]
    __nv_bfloat16* As = (__nv_bfloat16*)(dsm + 64*BSTRIDE*2); // [64][72]
    __shared__ unsigned hist[256];
    __shared__ unsigned sh_prefix, sh_k;
    __shared__ float red[8];

    const int bid = blockIdx.x;
    const int tid = threadIdx.x;
    const int lane = tid & 31, wid = tid >> 5;

    const int ntile = bid & 31;
    const int kc    = bid >> 5;
    const int n0    = ntile << 6;     // 64 cols per tile
    const int kbase = kc << 9;        // 512 K per chunk
    const int m     = bid;

    // zero recurrent state
    for (int i = bid * PTHREADS + tid; i < BATCH * REC; i += GRID * PTHREADS)
        g_Rh[i] = __float2bfloat16(0.0f);

    // load resident B slice: 64 rows x 512 cols
    #pragma unroll
    for (int i = 0; i < 16; i++) {
        int idx = tid + (i << 8);
        int row = idx >> 6, cu = (idx & 63) << 3;
        *(uint4*)&Bs[row * BSTRIDE + cu] =
            *(const uint4*)&g_WhT[(size_t)(n0 + row) * REC + kbase + cu];
    }
    unsigned baridx = 1;
    grid_barrier(baridx * GRID);

    // warp tile: 4 warps along M (16 rows), 2 along N (32 cols)
    const int m0w = (wid & 3) << 4;
    const int n0w = (wid >> 2) << 5;
    const unsigned sA = (unsigned)__cvta_generic_to_shared(As);
    const unsigned sB = (unsigned)__cvta_generic_to_shared(Bs);
    const unsigned lrow = (lane & 15);
    const unsigned lcol = (lane >> 4) << 3;
    const int ar0 = tid >> 3, ac0 = (tid & 7) << 3;   // A loader: 2 uint4/thread
    const int ar1 = ar0 + 32;

    for (int step = 0; step < RSTEPS; step++) {
        // ================= phase A: 64x64x512, B resident =================
        {
            float acc[4][4];
            #pragma unroll
            for (int f = 0; f < 4; f++)
                #pragma unroll
                for (int q = 0; q < 4; q++) acc[f][q] = 0.0f;

            uint4 pA[2];
            pA[0] = *(const uint4*)&g_Rh[(size_t)ar0 * REC + kbase + ac0];
            pA[1] = *(const uint4*)&g_Rh[(size_t)ar1 * REC + kbase + ac0];

            #pragma unroll 1
            for (int s = 0; s < 8; s++) {
                __syncthreads();
                *(uint4*)&As[ar0 * 72 + ac0] = pA[0];
                *(uint4*)&As[ar1 * 72 + ac0] = pA[1];
                __syncthreads();
                if (s + 1 < 8) {
                    const int kn = (s + 1) << 6;
                    pA[0] = *(const uint4*)&g_Rh[(size_t)ar0 * REC + kbase + kn + ac0];
                    pA[1] = *(const uint4*)&g_Rh[(size_t)ar1 * REC + kbase + kn + ac0];
                }
                unsigned Af[4][4];
                #pragma unroll
                for (int kst = 0; kst < 4; kst++) {
                    unsigned off = ((m0w + lrow) * 72 + (kst << 4) + lcol) << 1;
                    ldsm4v(Af[kst], sA + off);
                }
                #pragma unroll
                for (int kst = 0; kst < 4; kst++) {
                    #pragma unroll
                    for (int ng = 0; ng < 2; ng++) {
                        unsigned r[4];
                        unsigned off = ((n0w + (ng << 4) + lrow) * BSTRIDE +
                                        (s << 6) + (kst << 4) + lcol) << 1;
                        ldsm4v(r, sB + off);
                        mma16816(acc[2*ng],   Af[kst], r[0], r[2]);
                        mma16816(acc[2*ng+1], Af[kst], r[1], r[3]);
                    }
                }
            }

            const int g  = lane >> 2;
            const int tg = lane & 3;
            #pragma unroll
            for (int f = 0; f < 4; f++) {
                int coloff = n0 + n0w + (f << 3) + (tg << 1);
                int row0   = m0w + g;
                *(float2*)&g_part[((size_t)kc * BATCH + row0) * REC + coloff] =
                    make_float2(acc[f][0], acc[f][1]);
                *(float2*)&g_part[((size_t)kc * BATCH + row0 + 8) * REC + coloff] =
                    make_float2(acc[f][2], acc[f][3]);
            }
        }
        baridx++;
        grid_barrier(baridx * GRID);

        // ================= phase B =================
        if (bid < BATCH) {
            float zv[8], uv[8];
            hist[tid] = 0u;
            if (tid == 0) { sh_prefix = 0u; sh_k = KTOP; }
            __syncthreads();
            #pragma unroll
            for (int g2 = 0; g2 < 2; g2++) {
                const int j4 = (tid << 2) + (g2 << 10);
                float4 a = make_float4(0.f, 0.f, 0.f, 0.f);
                #pragma unroll
                for (int c = 0; c < 4; c++) {
                    float4 p = *(const float4*)&g_part[((size_t)c * BATCH + m) * REC + j4];
                    a.x += p.x; a.y += p.y; a.z += p.z; a.w += p.w;
                }
                zv[g2*4+0] = a.x; zv[g2*4+1] = a.y; zv[g2*4+2] = a.z; zv[g2*4+3] = a.w;
                float4 u4 = *(const float4*)&g_U[((size_t)step * BATCH + m) * REC + j4];
                uv[g2*4+0] = u4.x; uv[g2*4+1] = u4.y; uv[g2*4+2] = u4.z; uv[g2*4+3] = u4.w;
                atomicAdd(&hist[keyOf(a.x) >> 24], 1u);
                atomicAdd(&hist[keyOf(a.y) >> 24], 1u);
                atomicAdd(&hist[keyOf(a.z) >> 24], 1u);
                atomicAdd(&hist[keyOf(a.w) >> 24], 1u);
            }
            __syncthreads();
            bucket_select(hist, &sh_prefix, &sh_k, 24, tid);
            __syncthreads();
            #pragma unroll
            for (int pi = 0; pi < 3; pi++) {
                const int shift = 16 - (pi << 3);
                hist[tid] = 0u;
                __syncthreads();
                unsigned prefix = sh_prefix;
                unsigned maskH  = 0xFFFFFFFFu << (shift + 8);
                #pragma unroll
                for (int jj = 0; jj < 8; jj++) {
                    unsigned key = keyOf(zv[jj]);
                    if (((key ^ prefix) & maskH) == 0u)
                        atomicAdd(&hist[(key >> shift) & 0xFFu], 1u);
                }
                __syncthreads();
                bucket_select(hist, &sh_prefix, &sh_k, shift, tid);
                __syncthreads();
            }
            const unsigned thKey = sh_prefix;

            float part = 0.0f;
            #pragma unroll
            for (int jj = 0; jj < 8; jj++) {
                float zz = zv[jj];
                float sv = (keyOf(zz) >= thKey) ? zz : 0.0f;
                float v  = ftanh(uv[jj] + sv);
                zv[jj]   = v;
                part += v * v;
            }
            #pragma unroll
            for (int o = 16; o > 0; o >>= 1)
                part += __shfl_down_sync(0xFFFFFFFFu, part, o);
            if ((tid & 31) == 0) red[tid >> 5] = part;
            __syncthreads();
            if (tid < 32) {
                float v = (tid < 8) ? red[tid] : 0.0f;
                #pragma unroll
                for (int o = 4; o > 0; o >>= 1)
                    v += __shfl_down_sync(0xFFFFFFFFu, v, o);
                if (tid == 0) red[0] = v;
            }
            __syncthreads();
            const float inv = 1.0f / (sqrtf(red[0]) + 1e-6f);
            #pragma unroll
            for (int g2 = 0; g2 < 2; g2++) {
                const int j4 = (tid << 2) + (g2 << 10);
                float v0 = zv[g2*4+0] * inv, v1 = zv[g2*4+1] * inv;
                float v2 = zv[g2*4+2] * inv, v3 = zv[g2*4+3] * inv;
                __nv_bfloat162 hp0, hp1;
                hp0.x = __float2bfloat16(v0); hp0.y = __float2bfloat16(v1);
                hp1.x = __float2bfloat16(v2); hp1.y = __float2bfloat16(v3);
                *(__nv_bfloat162*)&g_Rh[(size_t)m * REC + j4]     = hp0;
                *(__nv_bfloat162*)&g_Rh[(size_t)m * REC + j4 + 2] = hp1;
                if (step == RSTEPS - 1)
                    *(float4*)&out[(size_t)m * REC + j4] = make_float4(v0, v1, v2, v3);
            }
        }
        baridx++;
        if (step < RSTEPS - 1) {
            grid_barrier(baridx * GRID);
        } else {
            __syncthreads();
            if (tid == 0) {
                __threadfence();
                unsigned p = atomicAdd(&g_bar, 1u);
                if (p == (unsigned)NBAR * GRID - 1u) atomicExch(&g_bar, 0u);
            }
        }
    }
}

// ---------------------------------------------------------------------------
extern "C" void kernel_launch(void* const* d_in, const int* in_sizes, int n_in,
                              void* d_out, int out_size)
{
    const float* x  = nullptr;   // 64*512*512  = 16777216
    const float* Wi = nullptr;   // 512*2048    = 1048576
    const float* Wr = nullptr;   // 2048*2048   = 4194304
    for (int i = 0; i < n_in; i++) {
        if      (in_sizes[i] == BATCH * RSTEPS * EDIM) x  = (const float*)d_in[i];
        else if (in_sizes[i] == EDIM * REC)            Wi = (const float*)d_in[i];
        else if (in_sizes[i] == REC * REC)             Wr = (const float*)d_in[i];
    }
    float* out = (float*)d_out;

    cudaFuncSetAttribute(persist_kernel,
                         cudaFuncAttributeMaxDynamicSharedMemorySize, DSMEM_BYTES);

    split_transpose_kernel<<<dim3(REC / 64, REC / 64), 256>>>(Wr, REC, REC, 0);
    split_transpose_kernel<<<dim3(REC / 64, EDIM / 64), 256>>>(Wi, EDIM, REC, 1);
    split_x_kernel<<<(BATCH * RSTEPS * EDIM) / 256, 256>>>(x);
    precompute_u_mma<<<dim3(REC / 128, RSTEPS), 256>>>();
    persist_kernel<<<GRID, PTHREADS, DSMEM_BYTES>>>(out);
}

// round 15
// speedup vs baseline: 1.3642x; 1.1511x over previous
#include <cuda_runtime.h>
#include <cuda_bf16.h>

#define REC      2048
#define BATCH    64
#define RSTEPS   512
#define EDIM     512
#define KTOP     819
#define GRID     128
#define PTHREADS 256
#define NBAR     (1 + 2*RSTEPS)
#define BSTRIDE  520                              // bf16 elems/row (1040B)
#define DSMEM_BYTES (2 * 64 * BSTRIDE * 2)        // Bs + As = 133120

// ---- static device scratch ----
__device__ __nv_bfloat16 g_Rh[BATCH * REC];
__device__ __nv_bfloat16 g_WhT[(size_t)REC * REC];
__device__ __nv_bfloat16 g_WlT[(size_t)REC * REC];
__device__ __nv_bfloat16 g_WiTh[(size_t)REC * EDIM];
__device__ __nv_bfloat16 g_WiTl[(size_t)REC * EDIM];
__device__ __nv_bfloat16 g_Xh[(size_t)BATCH * RSTEPS * EDIM];
__device__ __nv_bfloat16 g_Xl[(size_t)BATCH * RSTEPS * EDIM];
__device__ float g_part[4 * BATCH * REC];
__device__ float g_U[(size_t)RSTEPS * BATCH * REC];
__device__ unsigned g_bar;

__device__ __forceinline__ unsigned keyOf(float f) {
    unsigned b = __float_as_uint(f);
    return (b & 0x80000000u) ? ~b : (b | 0x80000000u);
}
__device__ __forceinline__ float ftanh(float x) {
    float t = __expf(2.0f * x);
    return 1.0f - __fdividef(2.0f, t + 1.0f);
}

// ---- tensor-core primitives (proven) ----
__device__ __forceinline__ void ldsm4v(unsigned* r, unsigned addr) {
    asm volatile("ldmatrix.sync.aligned.m8n8.x4.shared.b16 {%0,%1,%2,%3}, [%4];"
                 : "=r"(r[0]), "=r"(r[1]), "=r"(r[2]), "=r"(r[3]) : "r"(addr));
}
__device__ __forceinline__ void mma16816(float* d, const unsigned* a,
                                         unsigned b0, unsigned b1) {
    asm volatile("mma.sync.aligned.m16n8k16.row.col.f32.bf16.bf16.f32 "
                 "{%0,%1,%2,%3}, {%4,%5,%6,%7}, {%8,%9}, {%0,%1,%2,%3};"
                 : "+f"(d[0]), "+f"(d[1]), "+f"(d[2]), "+f"(d[3])
                 : "r"(a[0]), "r"(a[1]), "r"(a[2]), "r"(a[3]), "r"(b0), "r"(b1));
}

// ---- fence-free barrier primitives ----
__device__ __forceinline__ void bar_arrive_release() {
    asm volatile("red.release.gpu.global.add.u32 [%0], 1;"
                 :: "l"(&g_bar) : "memory");
}
__device__ __forceinline__ unsigned bar_poll_acquire() {
    unsigned v;
    asm volatile("ld.acquire.gpu.global.u32 %0, [%1];"
                 : "=r"(v) : "l"(&g_bar) : "memory");
    return v;
}
__device__ __forceinline__ void grid_barrier(unsigned target) {
    __syncthreads();
    if (threadIdx.x == 0) {
        bar_arrive_release();
        while (bar_poll_acquire() < target) { }
    }
    __syncthreads();
}

// ---------------------------------------------------------------------------
// 3-term tile (precompute): out = Ah@Bh + Al@Bh + Ah@Bl. (R11/R13-proven)
// ---------------------------------------------------------------------------
__device__ __forceinline__ void mma_tile_3term(
    const __nv_bfloat16* __restrict__ Ah, const __nv_bfloat16* __restrict__ Al,
    size_t strideA,
    const __nv_bfloat16* __restrict__ Bh, const __nv_bfloat16* __restrict__ Bl,
    size_t strideB,
    int nsub,
    float* __restrict__ outBase, size_t strideO,
    __nv_bfloat16 (*As_h)[72], __nv_bfloat16 (*As_l)[72], __nv_bfloat16 (*Bs)[72],
    int tid)
{
    const int lane = tid & 31, wid = tid >> 5;
    const int m0w = (wid & 3) << 4;
    const int n0w = (wid >> 2) << 6;
    const unsigned sAh = (unsigned)__cvta_generic_to_shared(&As_h[0][0]);
    const unsigned sAl = (unsigned)__cvta_generic_to_shared(&As_l[0][0]);
    const unsigned sB  = (unsigned)__cvta_generic_to_shared(&Bs[0][0]);
    const unsigned lrow = (lane & 15);
    const unsigned lcol = (lane >> 4) << 3;

    const int ar0 = tid >> 3, ac0 = (tid & 7) << 3;
    const int ar1 = (tid + 256) >> 3;
    const int br0 = tid >> 3;

    float acc[8][4];
    #pragma unroll
    for (int f = 0; f < 8; f++)
        #pragma unroll
        for (int q = 0; q < 4; q++) acc[f][q] = 0.0f;

    uint4 pAh[2], pAl[2], pBh[4], pBl[4];
    pAh[0] = *(const uint4*)&Ah[(size_t)ar0 * strideA + ac0];
    pAl[0] = *(const uint4*)&Al[(size_t)ar0 * strideA + ac0];
    pAh[1] = *(const uint4*)&Ah[(size_t)ar1 * strideA + ac0];
    pAl[1] = *(const uint4*)&Al[(size_t)ar1 * strideA + ac0];
    #pragma unroll
    for (int i = 0; i < 4; i++) {
        pBh[i] = *(const uint4*)&Bh[(size_t)(br0 + (i << 5)) * strideB + ac0];
        pBl[i] = *(const uint4*)&Bl[(size_t)(br0 + (i << 5)) * strideB + ac0];
    }

    #pragma unroll 1
    for (int s = 0; s < nsub; s++) {
        __syncthreads();
        *(uint4*)&As_h[ar0][ac0] = pAh[0];
        *(uint4*)&As_l[ar0][ac0] = pAl[0];
        *(uint4*)&As_h[ar1][ac0] = pAh[1];
        *(uint4*)&As_l[ar1][ac0] = pAl[1];
        #pragma unroll
        for (int i = 0; i < 4; i++)
            *(uint4*)&Bs[br0 + (i << 5)][ac0] = pBh[i];
        __syncthreads();

        if (s + 1 < nsub) {
            const int kn = (s + 1) << 6;
            pAh[0] = *(const uint4*)&Ah[(size_t)ar0 * strideA + kn + ac0];
            pAl[0] = *(const uint4*)&Al[(size_t)ar0 * strideA + kn + ac0];
            pAh[1] = *(const uint4*)&Ah[(size_t)ar1 * strideA + kn + ac0];
            pAl[1] = *(const uint4*)&Al[(size_t)ar1 * strideA + kn + ac0];
            #pragma unroll
            for (int i = 0; i < 4; i++)
                pBh[i] = *(const uint4*)&Bh[(size_t)(br0 + (i << 5)) * strideB + kn + ac0];
        }

        unsigned Afh[4][4], Afl[4][4];
        #pragma unroll
        for (int kst = 0; kst < 4; kst++) {
            unsigned off = ((m0w + lrow) * 72 + (kst << 4) + lcol) << 1;
            ldsm4v(Afh[kst], sAh + off);
            ldsm4v(Afl[kst], sAl + off);
        }
        #pragma unroll
        for (int kst = 0; kst < 4; kst++) {
            #pragma unroll
            for (int ng = 0; ng < 4; ng++) {
                unsigned r[4];
                unsigned off = ((n0w + (ng << 4) + lrow) * 72 + (kst << 4) + lcol) << 1;
                ldsm4v(r, sB + off);
                mma16816(acc[2*ng],   Afh[kst], r[0], r[2]);
                mma16816(acc[2*ng+1], Afh[kst], r[1], r[3]);
                mma16816(acc[2*ng],   Afl[kst], r[0], r[2]);
                mma16816(acc[2*ng+1], Afl[kst], r[1], r[3]);
            }
        }
        __syncthreads();
        #pragma unroll
        for (int i = 0; i < 4; i++)
            *(uint4*)&Bs[br0 + (i << 5)][ac0] = pBl[i];
        __syncthreads();
        if (s + 1 < nsub) {
            const int kn = (s + 1) << 6;
            #pragma unroll
            for (int i = 0; i < 4; i++)
                pBl[i] = *(const uint4*)&Bl[(size_t)(br0 + (i << 5)) * strideB + kn + ac0];
        }
        #pragma unroll
        for (int kst = 0; kst < 4; kst++) {
            #pragma unroll
            for (int ng = 0; ng < 4; ng++) {
                unsigned r[4];
                unsigned off = ((n0w + (ng << 4) + lrow) * 72 + (kst << 4) + lcol) << 1;
                ldsm4v(r, sB + off);
                mma16816(acc[2*ng],   Afh[kst], r[0], r[2]);
                mma16816(acc[2*ng+1], Afh[kst], r[1], r[3]);
            }
        }
    }

    const int g  = lane >> 2;
    const int tg = lane & 3;
    #pragma unroll
    for (int f = 0; f < 8; f++) {
        int coloff = n0w + (f << 3) + (tg << 1);
        int row0   = m0w + g;
        *(float2*)&outBase[(size_t)row0 * strideO + coloff] =
            make_float2(acc[f][0], acc[f][1]);
        *(float2*)&outBase[(size_t)(row0 + 8) * strideO + coloff] =
            make_float2(acc[f][2], acc[f][3]);
    }
}

// ---------------------------------------------------------------------------
// One-time splits.
// ---------------------------------------------------------------------------
__global__ void __launch_bounds__(256) split_transpose_kernel(
    const float* __restrict__ W, int Kdim, int Ndim, int mode)
{
    __shared__ float tile[64][65];
    __nv_bfloat16* outH = mode ? g_WiTh : g_WhT;
    __nv_bfloat16* outL = mode ? g_WiTl : g_WlT;
    const int k0 = blockIdx.y * 64, n0 = blockIdx.x * 64;
    const int tid = threadIdx.x;
    #pragma unroll
    for (int i = 0; i < 16; i++) {
        int idx = tid + (i << 8);
        int r = idx >> 6, c = idx & 63;
        tile[r][c] = W[(size_t)(k0 + r) * Ndim + n0 + c];
    }
    __syncthreads();
    #pragma unroll
    for (int i = 0; i < 16; i++) {
        int idx = tid + (i << 8);
        int nn = idx >> 6, kk = idx & 63;
        float w = tile[kk][nn];
        __nv_bfloat16 h = __float2bfloat16(w);
        outH[(size_t)(n0 + nn) * Kdim + (k0 + kk)] = h;
        outL[(size_t)(n0 + nn) * Kdim + (k0 + kk)] =
            __float2bfloat16(w - __bfloat162float(h));
    }
}

__global__ void __launch_bounds__(256) split_x_kernel(const float* __restrict__ x)
{
    size_t i = (size_t)blockIdx.x * 256 + threadIdx.x;
    float v = x[i];
    __nv_bfloat16 h = __float2bfloat16(v);
    g_Xh[i] = h;
    g_Xl[i] = __float2bfloat16(v - __bfloat162float(h));
}

// ---------------------------------------------------------------------------
// Precompute U = x @ W_input (3-term). grid (16, 512). 2 blocks/SM.
// ---------------------------------------------------------------------------
__global__ void __launch_bounds__(256, 2) precompute_u_mma()
{
    __shared__ __align__(16) __nv_bfloat16 As_h[64][72];
    __shared__ __align__(16) __nv_bfloat16 As_l[64][72];
    __shared__ __align__(16) __nv_bfloat16 Bs[128][72];
    const int t = blockIdx.y, n0 = blockIdx.x * 128, tid = threadIdx.x;
    mma_tile_3term(g_Xh + (size_t)t * EDIM, g_Xl + (size_t)t * EDIM,
                   (size_t)RSTEPS * EDIM,
                   g_WiTh + (size_t)n0 * EDIM, g_WiTl + (size_t)n0 * EDIM,
                   EDIM, EDIM / 64,
                   g_U + (size_t)t * BATCH * REC + n0, REC,
                   As_h, As_l, Bs, tid);
}

// ---------------------------------------------------------------------------
// Warp-parallel bucket select (proven).
// ---------------------------------------------------------------------------
__device__ __forceinline__ void bucket_select(
    unsigned* hist, unsigned* sh_prefix, unsigned* sh_k, int shift, int tid)
{
    if (tid < 32) {
        unsigned h[8], lsum = 0;
        int base = tid << 3;
        #pragma unroll
        for (int i = 0; i < 8; i++) { h[i] = hist[base + i]; lsum += h[i]; }
        unsigned inc = lsum;
        #pragma unroll
        for (int off = 16; off > 0; off >>= 1) {
            unsigned v = __shfl_down_sync(0xFFFFFFFFu, inc, off);
            if (tid + off < 32) inc += v;
        }
        unsigned k = *sh_k;
        unsigned above = inc - lsum;
        if (inc >= k && above < k) {
            unsigned S = above;
            #pragma unroll
            for (int i = 7; i >= 0; i--) {
                S += h[i];
                if (S >= k) {
                    *sh_k = k - (S - h[i]);
                    *sh_prefix |= ((unsigned)(base + i) << shift);
                    break;
                }
            }
        }
    }
}

// ---------------------------------------------------------------------------
// Persistent scan, 256 threads, 130 KB dynamic smem.
// Block bid: ntile = bid&31 (64 N-cols), kc = bid>>5 (512 K).
// Resident B: WhT slice [64 x 512] pinned all 512 steps.
// Phase A: SINGLE-stage A (full 64x512 in smem), 2 syncthreads, 128 MMA/warp.
// Cross-barrier global reads use __ldcg (L2-direct; barrier needs no L1 flush).
// ---------------------------------------------------------------------------
__global__ void __launch_bounds__(PTHREADS) persist_kernel(float* __restrict__ out)
{
    extern __shared__ __align__(16) char dsm[];
    __nv_bfloat16* Bs = (__nv_bfloat16*)dsm;                  // [64][BSTRIDE]
    __nv_bfloat16* As = (__nv_bfloat16*)(dsm + 64*BSTRIDE*2); // [64][BSTRIDE]
    __shared__ unsigned hist[256];
    __shared__ unsigned sh_prefix, sh_k;
    __shared__ float red[8];

    const int bid = blockIdx.x;
    const int tid = threadIdx.x;
    const int lane = tid & 31, wid = tid >> 5;

    const int ntile = bid & 31;
    const int kc    = bid >> 5;
    const int n0    = ntile << 6;
    const int kbase = kc << 9;
    const int m     = bid;

    for (int i = bid * PTHREADS + tid; i < BATCH * REC; i += GRID * PTHREADS)
        g_Rh[i] = __float2bfloat16(0.0f);

    // load resident B slice: 64 rows x 512 cols
    #pragma unroll
    for (int i = 0; i < 16; i++) {
        int idx = tid + (i << 8);
        int row = idx >> 6, cu = (idx & 63) << 3;
        *(uint4*)&Bs[row * BSTRIDE + cu] =
            *(const uint4*)&g_WhT[(size_t)(n0 + row) * REC + kbase + cu];
    }
    unsigned baridx = 1;
    grid_barrier(baridx * GRID);

    const int m0w = (wid & 3) << 4;
    const int n0w = (wid >> 2) << 5;
    const unsigned sA = (unsigned)__cvta_generic_to_shared(As);
    const unsigned sB = (unsigned)__cvta_generic_to_shared(Bs);
    const unsigned lrow = (lane & 15);
    const unsigned lcol = (lane >> 4) << 3;

    for (int step = 0; step < RSTEPS; step++) {
        // ========== phase A: 64x64x512, B resident, single A stage ==========
        {
            // load full A tile: 64x512 bf16 = 4096 uint4, 16/thread (L2-direct)
            uint4 pA[16];
            #pragma unroll
            for (int i = 0; i < 16; i++) {
                int idx = tid + (i << 8);
                int row = idx >> 6, cu = (idx & 63) << 3;
                pA[i] = __ldcg((const uint4*)&g_Rh[(size_t)row * REC + kbase + cu]);
            }
            #pragma unroll
            for (int i = 0; i < 16; i++) {
                int idx = tid + (i << 8);
                int row = idx >> 6, cu = (idx & 63) << 3;
                *(uint4*)&As[row * BSTRIDE + cu] = pA[i];
            }
            __syncthreads();

            float acc[4][4];
            #pragma unroll
            for (int f = 0; f < 4; f++)
                #pragma unroll
                for (int q = 0; q < 4; q++) acc[f][q] = 0.0f;

            #pragma unroll
            for (int s = 0; s < 8; s++) {
                unsigned Af[4][4];
                #pragma unroll
                for (int kst = 0; kst < 4; kst++) {
                    unsigned off = ((m0w + lrow) * BSTRIDE +
                                    (s << 6) + (kst << 4) + lcol) << 1;
                    ldsm4v(Af[kst], sA + off);
                }
                #pragma unroll
                for (int kst = 0; kst < 4; kst++) {
                    #pragma unroll
                    for (int ng = 0; ng < 2; ng++) {
                        unsigned r[4];
                        unsigned off = ((n0w + (ng << 4) + lrow) * BSTRIDE +
                                        (s << 6) + (kst << 4) + lcol) << 1;
                        ldsm4v(r, sB + off);
                        mma16816(acc[2*ng],   Af[kst], r[0], r[2]);
                        mma16816(acc[2*ng+1], Af[kst], r[1], r[3]);
                    }
                }
            }

            const int g  = lane >> 2;
            const int tg = lane & 3;
            #pragma unroll
            for (int f = 0; f < 4; f++) {
                int coloff = n0 + n0w + (f << 3) + (tg << 1);
                int row0   = m0w + g;
                *(float2*)&g_part[((size_t)kc * BATCH + row0) * REC + coloff] =
                    make_float2(acc[f][0], acc[f][1]);
                *(float2*)&g_part[((size_t)kc * BATCH + row0 + 8) * REC + coloff] =
                    make_float2(acc[f][2], acc[f][3]);
            }
            __syncthreads();   // As reads done before next step's overwrite
        }
        baridx++;
        grid_barrier(baridx * GRID);

        // ================= phase B =================
        if (bid < BATCH) {
            float zv[8], uv[8];
            hist[tid] = 0u;
            if (tid == 0) { sh_prefix = 0u; sh_k = KTOP; }
            __syncthreads();
            #pragma unroll
            for (int g2 = 0; g2 < 2; g2++) {
                const int j4 = (tid << 2) + (g2 << 10);
                float4 a = make_float4(0.f, 0.f, 0.f, 0.f);
                #pragma unroll
                for (int c = 0; c < 4; c++) {
                    float4 p = __ldcg((const float4*)&g_part[((size_t)c * BATCH + m) * REC + j4]);
                    a.x += p.x; a.y += p.y; a.z += p.z; a.w += p.w;
                }
                zv[g2*4+0] = a.x; zv[g2*4+1] = a.y; zv[g2*4+2] = a.z; zv[g2*4+3] = a.w;
                float4 u4 = __ldcg((const float4*)&g_U[((size_t)step * BATCH + m) * REC + j4]);
                uv[g2*4+0] = u4.x; uv[g2*4+1] = u4.y; uv[g2*4+2] = u4.z; uv[g2*4+3] = u4.w;
                atomicAdd(&hist[keyOf(a.x) >> 24], 1u);
                atomicAdd(&hist[keyOf(a.y) >> 24], 1u);
                atomicAdd(&hist[keyOf(a.z) >> 24], 1u);
                atomicAdd(&hist[keyOf(a.w) >> 24], 1u);
            }
            __syncthreads();
            bucket_select(hist, &sh_prefix, &sh_k, 24, tid);
            __syncthreads();
            #pragma unroll
            for (int pi = 0; pi < 3; pi++) {
                const int shift = 16 - (pi << 3);
                hist[tid] = 0u;
                __syncthreads();
                unsigned prefix = sh_prefix;
                unsigned maskH  = 0xFFFFFFFFu << (shift + 8);
                #pragma unroll
                for (int jj = 0; jj < 8; jj++) {
                    unsigned key = keyOf(zv[jj]);
                    if (((key ^ prefix) & maskH) == 0u)
                        atomicAdd(&hist[(key >> shift) & 0xFFu], 1u);
                }
                __syncthreads();
                bucket_select(hist, &sh_prefix, &sh_k, shift, tid);
                __syncthreads();
            }
            const unsigned thKey = sh_prefix;

            float part = 0.0f;
            #pragma unroll
            for (int jj = 0; jj < 8; jj++) {
                float zz = zv[jj];
                float sv = (keyOf(zz) >= thKey) ? zz : 0.0f;
                float v  = ftanh(uv[jj] + sv);
                zv[jj]   = v;
                part += v * v;
            }
            #pragma unroll
            for (int o = 16; o > 0; o >>= 1)
                part += __shfl_down_sync(0xFFFFFFFFu, part, o);
            if ((tid & 31) == 0) red[tid >> 5] = part;
            __syncthreads();
            if (tid < 32) {
                float v = (tid < 8) ? red[tid] : 0.0f;
                #pragma unroll
                for (int o = 4; o > 0; o >>= 1)
                    v += __shfl_down_sync(0xFFFFFFFFu, v, o);
                if (tid == 0) red[0] = v;
            }
            __syncthreads();
            const float inv = 1.0f / (sqrtf(red[0]) + 1e-6f);
            #pragma unroll
            for (int g2 = 0; g2 < 2; g2++) {
                const int j4 = (tid << 2) + (g2 << 10);
                float v0 = zv[g2*4+0] * inv, v1 = zv[g2*4+1] * inv;
                float v2 = zv[g2*4+2] * inv, v3 = zv[g2*4+3] * inv;
                __nv_bfloat162 hp0, hp1;
                hp0.x = __float2bfloat16(v0); hp0.y = __float2bfloat16(v1);
                hp1.x = __float2bfloat16(v2); hp1.y = __float2bfloat16(v3);
                *(__nv_bfloat162*)&g_Rh[(size_t)m * REC + j4]     = hp0;
                *(__nv_bfloat162*)&g_Rh[(size_t)m * REC + j4 + 2] = hp1;
                if (step == RSTEPS - 1)
                    *(float4*)&out[(size_t)m * REC + j4] = make_float4(v0, v1, v2, v3);
            }
        }
        baridx++;
        if (step < RSTEPS - 1) {
            grid_barrier(baridx * GRID);
        } else {
            __syncthreads();
            if (tid == 0) {
                __threadfence();
                unsigned p = atomicAdd(&g_bar, 1u);
                if (p == (unsigned)NBAR * GRID - 1u) atomicExch(&g_bar, 0u);
            }
        }
    }
}

// ---------------------------------------------------------------------------
extern "C" void kernel_launch(void* const* d_in, const int* in_sizes, int n_in,
                              void* d_out, int out_size)
{
    const float* x  = nullptr;   // 64*512*512  = 16777216
    const float* Wi = nullptr;   // 512*2048    = 1048576
    const float* Wr = nullptr;   // 2048*2048   = 4194304
    for (int i = 0; i < n_in; i++) {
        if      (in_sizes[i] == BATCH * RSTEPS * EDIM) x  = (const float*)d_in[i];
        else if (in_sizes[i] == EDIM * REC)            Wi = (const float*)d_in[i];
        else if (in_sizes[i] == REC * REC)             Wr = (const float*)d_in[i];
    }
    float* out = (float*)d_out;

    cudaFuncSetAttribute(persist_kernel,
                         cudaFuncAttributeMaxDynamicSharedMemorySize, DSMEM_BYTES);

    split_transpose_kernel<<<dim3(REC / 64, REC / 64), 256>>>(Wr, REC, REC, 0);
    split_transpose_kernel<<<dim3(REC / 64, EDIM / 64), 256>>>(Wi, EDIM, REC, 1);
    split_x_kernel<<<(BATCH * RSTEPS * EDIM) / 256, 256>>>(x);
    precompute_u_mma<<<dim3(REC / 128, RSTEPS), 256>>>();
    persist_kernel<<<GRID, PTHREADS, DSMEM_BYTES>>>(out);
}